// round 4
// baseline (speedup 1.0000x reference)
#include <cuda_runtime.h>
#include <math.h>

// Problem constants
#define T_DIM 4096
#define B_DIM 16
#define C_DIM 512
#define H_DIM 128
#define M_DIM (T_DIM*B_DIM)      // 65536 tokens
#define L_CHUNK 32
#define NC (T_DIM/L_CHUNK)       // 128 chunks
#define SA_PITCH 132             // padded A row pitch in floats (4-phase LDS.128)

// Scratch (static __device__ — no runtime allocation allowed)
__device__ float g_v[M_DIM*H_DIM];            // gated inputs v = sigmoid(g)*u, (t,b,h)
__device__ float g_ends[NC*B_DIM*H_DIM];      // local chunk-end states
__device__ float g_carry[NC*B_DIM*H_DIM];     // incoming true state per chunk
__device__ float g_pw0[H_DIM*H_DIM];          // matrix power ping
__device__ float g_pw1[H_DIM*H_DIM];          // matrix power pong

// ---------------- f32x2 packed-FMA helpers (sm_100+ PTX) ----------------
__device__ __forceinline__ unsigned long long pk2(float lo, float hi){
    unsigned long long r;
    asm("mov.b64 %0, {%1,%2};" : "=l"(r) : "f"(lo), "f"(hi));
    return r;
}
__device__ __forceinline__ void upk2(unsigned long long v, float &lo, float &hi){
    asm("mov.b64 {%0,%1}, %2;" : "=f"(lo), "=f"(hi) : "l"(v));
}
__device__ __forceinline__ void fma2(unsigned long long &d, unsigned long long a, unsigned long long b){
    asm("fma.rn.f32x2 %0, %1, %2, %0;" : "+l"(d) : "l"(a), "l"(b));
}

// ---------------- Kernel 1: fused projection GEMM -> v ----------------
// out tile: 64 tokens x 128 h (all h). 256 threads, thread tile 4 tok x 8 h,
// both u and gate accumulated as f32x2 pairs over h.
#define PRJ_BM 64
#define PRJ_BK 16
__global__ __launch_bounds__(256) void ssm_proj_kernel(
    const float* __restrict__ x,
    const float* __restrict__ Uw, const float* __restrict__ Ub,
    const float* __restrict__ Bw, const float* __restrict__ Bb)
{
    __shared__ float sx[PRJ_BK][PRJ_BM];     // [k][tok]
    __shared__ float su[PRJ_BK][H_DIM];      // [k][h]
    __shared__ float sg[PRJ_BK][H_DIM];

    const int tid = threadIdx.x;
    const int tx  = tid & 15;     // h group: h = tx*8 .. tx*8+7
    const int ty  = tid >> 4;     // tok group: tok = ty*4 .. ty*4+3
    const int row0 = blockIdx.x * PRJ_BM;

    unsigned long long au[4][4];  // [tok][h-pair]
    unsigned long long ag[4][4];
    #pragma unroll
    for(int i=0;i<4;i++)
        #pragma unroll
        for(int j=0;j<4;j++){ au[i][j]=0ull; ag[i][j]=0ull; }

    for(int k0=0;k0<C_DIM;k0+=PRJ_BK){
        // x tile: 64 tok x 16 k = 256 float4, one per thread
        {
            const int tok = tid >> 2, kq = tid & 3;
            const float4 vx = *(const float4*)(x + (size_t)(row0+tok)*C_DIM + k0 + 4*kq);
            sx[4*kq+0][tok]=vx.x; sx[4*kq+1][tok]=vx.y; sx[4*kq+2][tok]=vx.z; sx[4*kq+3][tok]=vx.w;
        }
        // weights: 128 h x 16 k per matrix = 512 float4 -> 2 per thread per matrix
        #pragma unroll
        for(int r=0;r<2;r++){
            const int idx = tid + 256*r;
            const int h = idx >> 2, kq = idx & 3;
            const float4 wu = *(const float4*)(Uw + (size_t)h*C_DIM + k0 + 4*kq);
            su[4*kq+0][h]=wu.x; su[4*kq+1][h]=wu.y; su[4*kq+2][h]=wu.z; su[4*kq+3][h]=wu.w;
            const float4 wg = *(const float4*)(Bw + (size_t)h*C_DIM + k0 + 4*kq);
            sg[4*kq+0][h]=wg.x; sg[4*kq+1][h]=wg.y; sg[4*kq+2][h]=wg.z; sg[4*kq+3][h]=wg.w;
        }
        __syncthreads();
        #pragma unroll
        for(int kk=0;kk<PRJ_BK;kk++){
            const float4 xa = *(const float4*)&sx[kk][ty*4];
            unsigned long long xp[4];
            xp[0]=pk2(xa.x,xa.x); xp[1]=pk2(xa.y,xa.y); xp[2]=pk2(xa.z,xa.z); xp[3]=pk2(xa.w,xa.w);
            const float4 wu0 = *(const float4*)&su[kk][tx*8];
            const float4 wu1 = *(const float4*)&su[kk][tx*8+4];
            const float4 wg0 = *(const float4*)&sg[kk][tx*8];
            const float4 wg1 = *(const float4*)&sg[kk][tx*8+4];
            unsigned long long up[4], gp[4];
            up[0]=pk2(wu0.x,wu0.y); up[1]=pk2(wu0.z,wu0.w); up[2]=pk2(wu1.x,wu1.y); up[3]=pk2(wu1.z,wu1.w);
            gp[0]=pk2(wg0.x,wg0.y); gp[1]=pk2(wg0.z,wg0.w); gp[2]=pk2(wg1.x,wg1.y); gp[3]=pk2(wg1.z,wg1.w);
            #pragma unroll
            for(int i=0;i<4;i++){
                #pragma unroll
                for(int j=0;j<4;j++){
                    fma2(au[i][j], xp[i], up[j]);
                    fma2(ag[i][j], xp[i], gp[j]);
                }
            }
        }
        __syncthreads();
    }
    // epilogue: add bias, sigmoid gate, write v
    float ub[8], gb[8];
    #pragma unroll
    for(int j=0;j<8;j++){ ub[j]=Ub[tx*8+j]; gb[j]=Bb[tx*8+j]; }
    #pragma unroll
    for(int i=0;i<4;i++){
        const int tok = row0 + ty*4 + i;
        float out[8];
        #pragma unroll
        for(int j=0;j<4;j++){
            float u0,u1,q0,q1;
            upk2(au[i][j],u0,u1); upk2(ag[i][j],q0,q1);
            u0 += ub[2*j]; u1 += ub[2*j+1];
            q0 += gb[2*j]; q1 += gb[2*j+1];
            const float s0 = 1.f/(1.f+__expf(-q0));
            const float s1 = 1.f/(1.f+__expf(-q1));
            out[2*j]   = s0*u0;
            out[2*j+1] = s1*u1;
        }
        float4* dst = (float4*)(g_v + (size_t)tok*H_DIM + tx*8);
        dst[0] = make_float4(out[0],out[1],out[2],out[3]);
        dst[1] = make_float4(out[4],out[5],out[6],out[7]);
    }
}

// ---------------- Kernel 2: 128x128 matrix square (for A^L) ----------------
__global__ __launch_bounds__(128) void ssm_matsq_kernel(const float* __restrict__ S,
                                                        float* __restrict__ D)
{
    __shared__ float row[H_DIM];
    const int i = blockIdx.x, j = threadIdx.x;
    row[j] = S[i*H_DIM + j];
    __syncthreads();
    float a0=0.f,a1=0.f,a2=0.f,a3=0.f;
    #pragma unroll 8
    for(int k=0;k<H_DIM;k+=4){
        a0 += row[k]   * S[(k  )*H_DIM + j];
        a1 += row[k+1] * S[(k+1)*H_DIM + j];
        a2 += row[k+2] * S[(k+2)*H_DIM + j];
        a3 += row[k+3] * S[(k+3)*H_DIM + j];
    }
    D[i*H_DIM + j] = (a0+a1)+(a2+a3);
}

// ---------------- Kernel 3: pass1 — local chunk scans ----------------
// grid = NC blocks, 128 threads; thread i computes output row i for all 16 b.
__global__ __launch_bounds__(128) void ssm_pass1_kernel(const float* __restrict__ Aw,
                                                        float* __restrict__ out)
{
    extern __shared__ float sm[];
    float* sA    = sm;                       // 128 x SA_PITCH
    float* hbuf0 = sm + H_DIM*SA_PITCH;      // 16 x 128
    float* hbuf1 = hbuf0 + B_DIM*H_DIM;
    const int i = threadIdx.x;
    const int c = blockIdx.x;

    #pragma unroll
    for(int j4=0;j4<32;j4++)
        *(float4*)&sA[i*SA_PITCH + 4*j4] = *(const float4*)(Aw + i*H_DIM + 4*j4);
    #pragma unroll
    for(int b=0;b<B_DIM;b++) hbuf0[b*H_DIM + i] = 0.f;
    __syncthreads();

    float* hc = hbuf0;
    float* hn = hbuf1;
    for(int k=0;k<L_CHUNK;k++){
        const int t = c*L_CHUNK + k;
        const float* vt = g_v + (size_t)t*(B_DIM*H_DIM);
        float vv[B_DIM];
        #pragma unroll
        for(int b=0;b<B_DIM;b++) vv[b] = vt[b*H_DIM + i];
        float acc[B_DIM];
        #pragma unroll
        for(int b=0;b<B_DIM;b++) acc[b] = 0.f;
        #pragma unroll 4
        for(int j4=0;j4<32;j4++){
            const float4 a4 = *(const float4*)&sA[i*SA_PITCH + 4*j4];
            #pragma unroll
            for(int b=0;b<B_DIM;b++){
                const float4 h4 = *(const float4*)&hc[b*H_DIM + 4*j4];
                acc[b] += a4.x*h4.x; acc[b] += a4.y*h4.y;
                acc[b] += a4.z*h4.z; acc[b] += a4.w*h4.w;
            }
        }
        float* ot = out + (size_t)t*(B_DIM*H_DIM);
        #pragma unroll
        for(int b=0;b<B_DIM;b++){
            const float r = acc[b] + vv[b];
            hn[b*H_DIM + i] = r;
            ot[b*H_DIM + i] = r;
        }
        __syncthreads();
        float* tmp = hc; hc = hn; hn = tmp;
    }
    #pragma unroll
    for(int b=0;b<B_DIM;b++)
        g_ends[(c*B_DIM+b)*H_DIM + i] = hc[b*H_DIM + i];
}

// ---------------- Kernel 4: pass2 — sequential carry chain (per batch row) ----------------
__global__ __launch_bounds__(128) void ssm_pass2_kernel()
{
    extern __shared__ float sm[];
    float* sAL = sm;                          // A^L, 128 x SA_PITCH
    __shared__ float sP[H_DIM];
    const int i = threadIdx.x;
    const int b = blockIdx.x;
    #pragma unroll
    for(int j4=0;j4<32;j4++)
        *(float4*)&sAL[i*SA_PITCH + 4*j4] = *(const float4*)(g_pw0 + i*H_DIM + 4*j4);
    sP[i] = 0.f;
    __syncthreads();
    for(int c=0;c<NC;c++){
        g_carry[(c*B_DIM+b)*H_DIM + i] = sP[i];          // incoming state for chunk c
        float a0=0.f,a1=0.f,a2=0.f,a3=0.f;
        #pragma unroll 8
        for(int j4=0;j4<32;j4++){
            const float4 a4 = *(const float4*)&sAL[i*SA_PITCH + 4*j4];
            const float4 p4 = *(const float4*)&sP[4*j4];
            a0 += a4.x*p4.x; a1 += a4.y*p4.y; a2 += a4.z*p4.z; a3 += a4.w*p4.w;
        }
        const float e = g_ends[(c*B_DIM+b)*H_DIM + i];
        const float nv = e + ((a0+a1)+(a2+a3));
        __syncthreads();
        sP[i] = nv;
        __syncthreads();
    }
}

// ---------------- Kernel 5: pass3 — fixup h_t += A^{k+1} * carry ----------------
__global__ __launch_bounds__(128) void ssm_pass3_kernel(const float* __restrict__ Aw,
                                                        float* __restrict__ out)
{
    extern __shared__ float sm[];
    float* sA = sm;
    float* g0 = sm + H_DIM*SA_PITCH;
    float* g1 = g0 + B_DIM*H_DIM;
    const int i = threadIdx.x;
    const int c = blockIdx.x + 1;             // chunk 0 has zero carry

    #pragma unroll
    for(int j4=0;j4<32;j4++)
        *(float4*)&sA[i*SA_PITCH + 4*j4] = *(const float4*)(Aw + i*H_DIM + 4*j4);
    #pragma unroll
    for(int b=0;b<B_DIM;b++) g0[b*H_DIM + i] = g_carry[(c*B_DIM+b)*H_DIM + i];
    __syncthreads();

    float* gc = g0;
    float* gn = g1;
    for(int k=0;k<L_CHUNK;k++){
        const int t = c*L_CHUNK + k;
        float* ot = out + (size_t)t*(B_DIM*H_DIM);
        float ov[B_DIM];
        #pragma unroll
        for(int b=0;b<B_DIM;b++) ov[b] = ot[b*H_DIM + i];
        float acc[B_DIM];
        #pragma unroll
        for(int b=0;b<B_DIM;b++) acc[b] = 0.f;
        #pragma unroll 4
        for(int j4=0;j4<32;j4++){
            const float4 a4 = *(const float4*)&sA[i*SA_PITCH + 4*j4];
            #pragma unroll
            for(int b=0;b<B_DIM;b++){
                const float4 h4 = *(const float4*)&gc[b*H_DIM + 4*j4];
                acc[b] += a4.x*h4.x; acc[b] += a4.y*h4.y;
                acc[b] += a4.z*h4.z; acc[b] += a4.w*h4.w;
            }
        }
        #pragma unroll
        for(int b=0;b<B_DIM;b++){
            gn[b*H_DIM + i] = acc[b];
            ot[b*H_DIM + i] = ov[b] + acc[b];
        }
        __syncthreads();
        float* tmp = gc; gc = gn; gn = tmp;
    }
}

// ---------------- launch ----------------
extern "C" void kernel_launch(void* const* d_in, const int* in_sizes, int n_in,
                              void* d_out, int out_size)
{
    const float* x  = (const float*)d_in[0];
    const float* Uw = (const float*)d_in[1];
    const float* Ub = (const float*)d_in[2];
    const float* Bw = (const float*)d_in[3];
    const float* Bb = (const float*)d_in[4];
    const float* Aw = (const float*)d_in[5];
    float* out = (float*)d_out;

    const int smem_pass = (H_DIM*SA_PITCH + 2*B_DIM*H_DIM) * 4;   // 83968 B
    const int smem_p2   = (H_DIM*SA_PITCH) * 4;                    // 67584 B
    cudaFuncSetAttribute(ssm_pass1_kernel, cudaFuncAttributeMaxDynamicSharedMemorySize, smem_pass);
    cudaFuncSetAttribute(ssm_pass3_kernel, cudaFuncAttributeMaxDynamicSharedMemorySize, smem_pass);
    cudaFuncSetAttribute(ssm_pass2_kernel, cudaFuncAttributeMaxDynamicSharedMemorySize, smem_p2);

    // 1) projection -> v
    ssm_proj_kernel<<<M_DIM/PRJ_BM, 256>>>(x, Uw, Ub, Bw, Bb);

    // 2) A^32 via 5 squarings (ping-pong), result in g_pw0
    void *pw0_v, *pw1_v;
    cudaGetSymbolAddress(&pw0_v, g_pw0);
    cudaGetSymbolAddress(&pw1_v, g_pw1);
    float* pw0 = (float*)pw0_v;
    float* pw1 = (float*)pw1_v;
    ssm_matsq_kernel<<<H_DIM,H_DIM>>>(Aw,  pw0);   // A^2
    ssm_matsq_kernel<<<H_DIM,H_DIM>>>(pw0, pw1);   // A^4
    ssm_matsq_kernel<<<H_DIM,H_DIM>>>(pw1, pw0);   // A^8
    ssm_matsq_kernel<<<H_DIM,H_DIM>>>(pw0, pw1);   // A^16
    ssm_matsq_kernel<<<H_DIM,H_DIM>>>(pw1, pw0);   // A^32

    // 3) local scans
    ssm_pass1_kernel<<<NC, 128, smem_pass>>>(Aw, out);
    // 4) carry chain (parallel over batch rows)
    ssm_pass2_kernel<<<B_DIM, 128, smem_p2>>>();
    // 5) fixup
    ssm_pass3_kernel<<<NC-1, 128, smem_pass>>>(Aw, out);
}

// round 9
// speedup vs baseline: 1.0095x; 1.0095x over previous
#include <cuda_runtime.h>
#include <math.h>
#include <stdint.h>

// Problem constants
#define T_DIM 4096
#define B_DIM 16
#define C_DIM 512
#define H_DIM 128
#define M_DIM (T_DIM*B_DIM)      // 65536 tokens
#define L_CHUNK 32
#define NC (T_DIM/L_CHUNK)       // 128 chunks
#define SA_PITCH 132             // padded A row pitch in floats (4-phase LDS.128)

// Scratch (static __device__ — no runtime allocation allowed)
__device__ float g_v[M_DIM*H_DIM];            // gated inputs v = sigmoid(g)*u, (t,b,h)
__device__ float g_ends[NC*B_DIM*H_DIM];      // local chunk-end states
__device__ float g_carry[NC*B_DIM*H_DIM];     // incoming true state per chunk
__device__ float g_pw0[H_DIM*H_DIM];          // matrix power ping
__device__ float g_pw1[H_DIM*H_DIM];          // matrix power pong

// ---------------- f32x2 packed-FMA helpers (base sm_100+ PTX, not 'a'-gated) ----------------
__device__ __forceinline__ unsigned long long pk2(float lo, float hi){
    unsigned long long r;
    asm("mov.b64 %0, {%1,%2};" : "=l"(r) : "f"(lo), "f"(hi));
    return r;
}
__device__ __forceinline__ void upk2(unsigned long long v, float &lo, float &hi){
    asm("mov.b64 {%0,%1}, %2;" : "=f"(lo), "=f"(hi) : "l"(v));
}
__device__ __forceinline__ void fma2(unsigned long long &d, unsigned long long a, unsigned long long b){
    asm("fma.rn.f32x2 %0, %1, %2, %0;" : "+l"(d) : "l"(a), "l"(b));
}

// ---------------- Kernel 1: fused projection GEMM -> v (f32x2, R4-proven) ----------------
// out tile: 64 tokens x 128 h (all h). 256 threads, thread tile 4 tok x 8 h,
// both u and gate accumulated as f32x2 pairs over h.
#define PRJ_BM 64
#define PRJ_BK 16
__global__ __launch_bounds__(256) void ssm_proj_kernel(
    const float* __restrict__ x,
    const float* __restrict__ Uw, const float* __restrict__ Ub,
    const float* __restrict__ Bw, const float* __restrict__ Bb)
{
    __shared__ float sx[PRJ_BK][PRJ_BM];     // [k][tok]
    __shared__ float su[PRJ_BK][H_DIM];      // [k][h]
    __shared__ float sg[PRJ_BK][H_DIM];

    const int tid = threadIdx.x;
    const int tx  = tid & 15;     // h group: h = tx*8 .. tx*8+7
    const int ty  = tid >> 4;     // tok group: tok = ty*4 .. ty*4+3
    const int row0 = blockIdx.x * PRJ_BM;

    unsigned long long au[4][4];  // [tok][h-pair]
    unsigned long long ag[4][4];
    #pragma unroll
    for(int i=0;i<4;i++)
        #pragma unroll
        for(int j=0;j<4;j++){ au[i][j]=0ull; ag[i][j]=0ull; }

    for(int k0=0;k0<C_DIM;k0+=PRJ_BK){
        // x tile: 64 tok x 16 k = 256 float4, one per thread
        {
            const int tok = tid >> 2, kq = tid & 3;
            const float4 vx = *(const float4*)(x + (size_t)(row0+tok)*C_DIM + k0 + 4*kq);
            sx[4*kq+0][tok]=vx.x; sx[4*kq+1][tok]=vx.y; sx[4*kq+2][tok]=vx.z; sx[4*kq+3][tok]=vx.w;
        }
        // weights: 128 h x 16 k per matrix = 512 float4 -> 2 per thread per matrix
        #pragma unroll
        for(int r=0;r<2;r++){
            const int idx = tid + 256*r;
            const int h = idx >> 2, kq = idx & 3;
            const float4 wu = *(const float4*)(Uw + (size_t)h*C_DIM + k0 + 4*kq);
            su[4*kq+0][h]=wu.x; su[4*kq+1][h]=wu.y; su[4*kq+2][h]=wu.z; su[4*kq+3][h]=wu.w;
            const float4 wg = *(const float4*)(Bw + (size_t)h*C_DIM + k0 + 4*kq);
            sg[4*kq+0][h]=wg.x; sg[4*kq+1][h]=wg.y; sg[4*kq+2][h]=wg.z; sg[4*kq+3][h]=wg.w;
        }
        __syncthreads();
        #pragma unroll
        for(int kk=0;kk<PRJ_BK;kk++){
            const float4 xa = *(const float4*)&sx[kk][ty*4];
            unsigned long long xp[4];
            xp[0]=pk2(xa.x,xa.x); xp[1]=pk2(xa.y,xa.y); xp[2]=pk2(xa.z,xa.z); xp[3]=pk2(xa.w,xa.w);
            const float4 wu0 = *(const float4*)&su[kk][tx*8];
            const float4 wu1 = *(const float4*)&su[kk][tx*8+4];
            const float4 wg0 = *(const float4*)&sg[kk][tx*8];
            const float4 wg1 = *(const float4*)&sg[kk][tx*8+4];
            unsigned long long up[4], gp[4];
            up[0]=pk2(wu0.x,wu0.y); up[1]=pk2(wu0.z,wu0.w); up[2]=pk2(wu1.x,wu1.y); up[3]=pk2(wu1.z,wu1.w);
            gp[0]=pk2(wg0.x,wg0.y); gp[1]=pk2(wg0.z,wg0.w); gp[2]=pk2(wg1.x,wg1.y); gp[3]=pk2(wg1.z,wg1.w);
            #pragma unroll
            for(int i=0;i<4;i++){
                #pragma unroll
                for(int j=0;j<4;j++){
                    fma2(au[i][j], xp[i], up[j]);
                    fma2(ag[i][j], xp[i], gp[j]);
                }
            }
        }
        __syncthreads();
    }
    // epilogue: add bias, sigmoid gate, write v
    float ub[8], gb[8];
    #pragma unroll
    for(int j=0;j<8;j++){ ub[j]=Ub[tx*8+j]; gb[j]=Bb[tx*8+j]; }
    #pragma unroll
    for(int i=0;i<4;i++){
        const int tok = row0 + ty*4 + i;
        float out[8];
        #pragma unroll
        for(int j=0;j<4;j++){
            float u0,u1,q0,q1;
            upk2(au[i][j],u0,u1); upk2(ag[i][j],q0,q1);
            u0 += ub[2*j]; u1 += ub[2*j+1];
            q0 += gb[2*j]; q1 += gb[2*j+1];
            const float s0 = 1.f/(1.f+__expf(-q0));
            const float s1 = 1.f/(1.f+__expf(-q1));
            out[2*j]   = s0*u0;
            out[2*j+1] = s1*u1;
        }
        float4* dst = (float4*)(g_v + (size_t)tok*H_DIM + tx*8);
        dst[0] = make_float4(out[0],out[1],out[2],out[3]);
        dst[1] = make_float4(out[4],out[5],out[6],out[7]);
    }
}

// ---------------- Kernel 2: 128x128 matrix square (for A^L) ----------------
__global__ __launch_bounds__(128) void ssm_matsq_kernel(const float* __restrict__ S,
                                                        float* __restrict__ D)
{
    __shared__ float row[H_DIM];
    const int i = blockIdx.x, j = threadIdx.x;
    row[j] = S[i*H_DIM + j];
    __syncthreads();
    float a0=0.f,a1=0.f,a2=0.f,a3=0.f;
    #pragma unroll 8
    for(int k=0;k<H_DIM;k+=4){
        a0 += row[k]   * S[(k  )*H_DIM + j];
        a1 += row[k+1] * S[(k+1)*H_DIM + j];
        a2 += row[k+2] * S[(k+2)*H_DIM + j];
        a3 += row[k+3] * S[(k+3)*H_DIM + j];
    }
    D[i*H_DIM + j] = (a0+a1)+(a2+a3);
}

// ---------------- Kernel 3: pass1 — local chunk scans (f32x2) ----------------
// grid = NC blocks, 128 threads; thread i computes output row i for all 16 b.
__global__ __launch_bounds__(128) void ssm_pass1_kernel(const float* __restrict__ Aw,
                                                        float* __restrict__ out)
{
    extern __shared__ float sm[];
    float* sA    = sm;                       // 128 x SA_PITCH
    float* hbuf0 = sm + H_DIM*SA_PITCH;      // 16 x 128
    float* hbuf1 = hbuf0 + B_DIM*H_DIM;
    const int i = threadIdx.x;
    const int c = blockIdx.x;

    #pragma unroll
    for(int j4=0;j4<32;j4++)
        *(float4*)&sA[i*SA_PITCH + 4*j4] = *(const float4*)(Aw + i*H_DIM + 4*j4);
    #pragma unroll
    for(int b=0;b<B_DIM;b++) hbuf0[b*H_DIM + i] = 0.f;
    __syncthreads();

    float* hc = hbuf0;
    float* hn = hbuf1;
    for(int k=0;k<L_CHUNK;k++){
        const int t = c*L_CHUNK + k;
        const float* vt = g_v + (size_t)t*(B_DIM*H_DIM);
        float vv[B_DIM];
        #pragma unroll
        for(int b=0;b<B_DIM;b++) vv[b] = vt[b*H_DIM + i];
        unsigned long long acc[B_DIM];
        #pragma unroll
        for(int b=0;b<B_DIM;b++) acc[b] = 0ull;
        #pragma unroll 4
        for(int j4=0;j4<32;j4++){
            const ulonglong2 a2 = *(const ulonglong2*)&sA[i*SA_PITCH + 4*j4];
            #pragma unroll
            for(int b=0;b<B_DIM;b++){
                const ulonglong2 h2 = *(const ulonglong2*)&hc[b*H_DIM + 4*j4];
                fma2(acc[b], a2.x, h2.x);
                fma2(acc[b], a2.y, h2.y);
            }
        }
        float* ot = out + (size_t)t*(B_DIM*H_DIM);
        #pragma unroll
        for(int b=0;b<B_DIM;b++){
            float lo, hi;
            upk2(acc[b], lo, hi);
            const float r = (lo + hi) + vv[b];
            hn[b*H_DIM + i] = r;
            ot[b*H_DIM + i] = r;
        }
        __syncthreads();
        float* tmp = hc; hc = hn; hn = tmp;
    }
    #pragma unroll
    for(int b=0;b<B_DIM;b++)
        g_ends[(c*B_DIM+b)*H_DIM + i] = hc[b*H_DIM + i];
}

// ---------------- Kernel 4: pass2 — carry chain, fully smem-resident ----------------
// grid = B_DIM blocks, 128 threads. A^L and all 128 chunk-end vectors preloaded
// into smem; the 128-long serial chain never touches gmem on the critical path
// (only the g_carry stores, which nothing in this kernel reads back).
__global__ __launch_bounds__(128) void ssm_pass2_kernel()
{
    extern __shared__ float sm[];
    float* sAL = sm;                          // A^L, 128 x SA_PITCH
    float* sE  = sm + H_DIM*SA_PITCH;         // all chunk ends for this batch: 128 x 128
    __shared__ float sP[H_DIM];
    const int i = threadIdx.x;
    const int b = blockIdx.x;

    #pragma unroll
    for(int j4=0;j4<32;j4++)
        *(float4*)&sAL[i*SA_PITCH + 4*j4] = *(const float4*)(g_pw0 + i*H_DIM + 4*j4);
    #pragma unroll 8
    for(int c=0;c<NC;c++)
        sE[c*H_DIM + i] = g_ends[(c*B_DIM+b)*H_DIM + i];
    sP[i] = 0.f;
    float cur = 0.f;
    __syncthreads();

    for(int c=0;c<NC;c++){
        g_carry[(c*B_DIM+b)*H_DIM + i] = cur;          // incoming state for chunk c
        unsigned long long a0 = 0ull, a1 = 0ull;
        #pragma unroll 8
        for(int j4=0;j4<32;j4++){
            const ulonglong2 a2 = *(const ulonglong2*)&sAL[i*SA_PITCH + 4*j4];
            const ulonglong2 p2 = *(const ulonglong2*)&sP[4*j4];
            fma2(a0, a2.x, p2.x);
            fma2(a1, a2.y, p2.y);
        }
        float l0,h0,l1,h1;
        upk2(a0,l0,h0); upk2(a1,l1,h1);
        cur = sE[c*H_DIM + i] + ((l0+h0)+(l1+h1));
        __syncthreads();
        sP[i] = cur;
        __syncthreads();
    }
}

// ---------------- Kernel 5: pass3 — fixup h_t += A^{k+1} * carry (f32x2) ----------------
__global__ __launch_bounds__(128) void ssm_pass3_kernel(const float* __restrict__ Aw,
                                                        float* __restrict__ out)
{
    extern __shared__ float sm[];
    float* sA = sm;
    float* g0 = sm + H_DIM*SA_PITCH;
    float* g1 = g0 + B_DIM*H_DIM;
    const int i = threadIdx.x;
    const int c = blockIdx.x + 1;             // chunk 0 has zero carry

    #pragma unroll
    for(int j4=0;j4<32;j4++)
        *(float4*)&sA[i*SA_PITCH + 4*j4] = *(const float4*)(Aw + i*H_DIM + 4*j4);
    #pragma unroll
    for(int b=0;b<B_DIM;b++) g0[b*H_DIM + i] = g_carry[(c*B_DIM+b)*H_DIM + i];
    __syncthreads();

    float* gc = g0;
    float* gn = g1;
    for(int k=0;k<L_CHUNK;k++){
        const int t = c*L_CHUNK + k;
        float* ot = out + (size_t)t*(B_DIM*H_DIM);
        float ov[B_DIM];
        #pragma unroll
        for(int b=0;b<B_DIM;b++) ov[b] = ot[b*H_DIM + i];
        unsigned long long acc[B_DIM];
        #pragma unroll
        for(int b=0;b<B_DIM;b++) acc[b] = 0ull;
        #pragma unroll 4
        for(int j4=0;j4<32;j4++){
            const ulonglong2 a2 = *(const ulonglong2*)&sA[i*SA_PITCH + 4*j4];
            #pragma unroll
            for(int b=0;b<B_DIM;b++){
                const ulonglong2 h2 = *(const ulonglong2*)&gc[b*H_DIM + 4*j4];
                fma2(acc[b], a2.x, h2.x);
                fma2(acc[b], a2.y, h2.y);
            }
        }
        #pragma unroll
        for(int b=0;b<B_DIM;b++){
            float lo, hi;
            upk2(acc[b], lo, hi);
            const float r = lo + hi;
            gn[b*H_DIM + i] = r;
            ot[b*H_DIM + i] = ov[b] + r;
        }
        __syncthreads();
        float* tmp = gc; gc = gn; gn = tmp;
    }
}

// ---------------- launch ----------------
extern "C" void kernel_launch(void* const* d_in, const int* in_sizes, int n_in,
                              void* d_out, int out_size)
{
    const float* x  = (const float*)d_in[0];
    const float* Uw = (const float*)d_in[1];
    const float* Ub = (const float*)d_in[2];
    const float* Bw = (const float*)d_in[3];
    const float* Bb = (const float*)d_in[4];
    const float* Aw = (const float*)d_in[5];
    float* out = (float*)d_out;

    const int smem_pass = (H_DIM*SA_PITCH + 2*B_DIM*H_DIM) * 4;   // 83968 B
    const int smem_p2   = (H_DIM*SA_PITCH + NC*H_DIM) * 4;        // 133120 B
    cudaFuncSetAttribute(ssm_pass1_kernel, cudaFuncAttributeMaxDynamicSharedMemorySize, smem_pass);
    cudaFuncSetAttribute(ssm_pass3_kernel, cudaFuncAttributeMaxDynamicSharedMemorySize, smem_pass);
    cudaFuncSetAttribute(ssm_pass2_kernel, cudaFuncAttributeMaxDynamicSharedMemorySize, smem_p2);

    // 1) projection -> v
    ssm_proj_kernel<<<M_DIM/PRJ_BM, 256>>>(x, Uw, Ub, Bw, Bb);

    // 2) A^32 via 5 squarings (ping-pong), result in g_pw0
    void *pw0_v, *pw1_v;
    cudaGetSymbolAddress(&pw0_v, g_pw0);
    cudaGetSymbolAddress(&pw1_v, g_pw1);
    float* pw0 = (float*)pw0_v;
    float* pw1 = (float*)pw1_v;
    ssm_matsq_kernel<<<H_DIM,H_DIM>>>(Aw,  pw0);   // A^2
    ssm_matsq_kernel<<<H_DIM,H_DIM>>>(pw0, pw1);   // A^4
    ssm_matsq_kernel<<<H_DIM,H_DIM>>>(pw1, pw0);   // A^8
    ssm_matsq_kernel<<<H_DIM,H_DIM>>>(pw0, pw1);   // A^16
    ssm_matsq_kernel<<<H_DIM,H_DIM>>>(pw1, pw0);   // A^32

    // 3) local scans
    ssm_pass1_kernel<<<NC, 128, smem_pass>>>(Aw, out);
    // 4) carry chain (parallel over batch rows, smem-resident)
    ssm_pass2_kernel<<<B_DIM, 128, smem_p2>>>();
    // 5) fixup
    ssm_pass3_kernel<<<NC-1, 128, smem_pass>>>(Aw, out);
}

// round 11
// speedup vs baseline: 2.0253x; 2.0061x over previous
#include <cuda_runtime.h>
#include <math.h>
#include <stdint.h>

// Problem constants
#define T_DIM 4096
#define B_DIM 16
#define C_DIM 512
#define H_DIM 128
#define M_DIM (T_DIM*B_DIM)      // 65536 tokens
#define L_CHUNK 32
#define NC (T_DIM/L_CHUNK)       // 128 chunks
#define SA_PITCH 132             // padded A row pitch in floats

// Scratch (static __device__ — no runtime allocation allowed)
__device__ float g_v[M_DIM*H_DIM];            // gated inputs v = sigmoid(g)*u, (t,b,h)
__device__ float g_ends[NC*B_DIM*H_DIM];      // local chunk-end states
__device__ float g_carry[NC*B_DIM*H_DIM];     // incoming true state per chunk
__device__ float g_pw0[H_DIM*H_DIM];          // matrix power ping
__device__ float g_pw1[H_DIM*H_DIM];          // matrix power pong

// ---------------- f32x2 packed-FMA helpers ----------------
__device__ __forceinline__ void upk2(unsigned long long v, float &lo, float &hi){
    asm("mov.b64 {%0,%1}, %2;" : "=f"(lo), "=f"(hi) : "l"(v));
}
__device__ __forceinline__ void fma2(unsigned long long &d, unsigned long long a, unsigned long long b){
    asm("fma.rn.f32x2 %0, %1, %2, %0;" : "+l"(d) : "l"(a), "l"(b));
}

// ---------------- bf16 split + mma.sync helpers (base ISA, no 'a' features) ----------------
// pack two floats to bf16x2 (low half = first arg) and the bf16 residuals
__device__ __forceinline__ void split2(float a, float b, uint32_t &hi, uint32_t &lo){
    asm("cvt.rn.bf16x2.f32 %0, %1, %2;" : "=r"(hi) : "f"(b), "f"(a));
    const float ha = __uint_as_float(hi << 16);
    const float hb = __uint_as_float(hi & 0xffff0000u);
    const float ra = a - ha, rb = b - hb;
    asm("cvt.rn.bf16x2.f32 %0, %1, %2;" : "=r"(lo) : "f"(rb), "f"(ra));
}
__device__ __forceinline__ void mma_bf16(float* c, const uint32_t* a, const uint32_t* b){
    asm volatile("mma.sync.aligned.m16n8k16.row.col.f32.bf16.bf16.f32 "
                 "{%0,%1,%2,%3}, {%4,%5,%6,%7}, {%8,%9}, {%0,%1,%2,%3};"
                 : "+f"(c[0]), "+f"(c[1]), "+f"(c[2]), "+f"(c[3])
                 : "r"(a[0]), "r"(a[1]), "r"(a[2]), "r"(a[3]), "r"(b[0]), "r"(b[1]));
}

// ---------------- Kernel 1: tensor-core projection GEMM -> v ----------------
// Per CTA: 128 tokens x (u:128 | g:128) outputs, K=512 in 8 tiles of 64.
// bf16 hi/lo split, 3 accumulating terms. Warp tile: 64 tok x 32 h (u AND g).
#define KP 72                      // smem row pitch in bf16 (64 + 8 pad)
#define XTILE_W32 (128*36)         // sX tile size in u32 words (128 rows * KP/2)
#define WTILE_W32 (256*36)         // sW tile size in u32 words
// dynamic smem words: sXh | sXl | sWh | sWl
#define PROJ_SMEM_BYTES ((2*XTILE_W32 + 2*WTILE_W32)*4)   // 110592

extern __shared__ uint32_t proj_sm[];

__global__ __launch_bounds__(256) void ssm_proj_mma(
    const float* __restrict__ x,
    const float* __restrict__ Uw, const float* __restrict__ Ub,
    const float* __restrict__ Bw, const float* __restrict__ Bb)
{
    uint32_t* sXh = proj_sm;
    uint32_t* sXl = proj_sm + XTILE_W32;
    uint32_t* sWh = proj_sm + 2*XTILE_W32;
    uint32_t* sWl = proj_sm + 2*XTILE_W32 + WTILE_W32;

    const int tid  = threadIdx.x;
    const int wid  = tid >> 5;
    const int lane = tid & 31;
    const int lr   = lane >> 2;       // fragment row 0-7
    const int lc   = lane & 3;        // fragment col-pair 0-3
    const int row0 = blockIdx.x * 128;
    const int mbase = (wid & 1) * 64;     // warp m origin (tokens)
    const int hbase = (wid >> 1) * 32;    // warp h origin (output features)

    // accumulators: [mi 0..3][ni 0..3][4], for u and g
    float cu[4][4][4];
    float cg[4][4][4];
    #pragma unroll
    for(int mi=0;mi<4;mi++)
        #pragma unroll
        for(int ni=0;ni<4;ni++)
            #pragma unroll
            for(int e=0;e<4;e++){ cu[mi][ni][e]=0.f; cg[mi][ni][e]=0.f; }

    for(int kt=0;kt<8;kt++){
        const int kbase = kt*64;
        __syncthreads();
        // ---- load x tile: 128 rows x 64 k (2048 float4, 8 per thread) ----
        #pragma unroll
        for(int it=0;it<8;it++){
            const int linear = tid + 256*it;
            const int row = linear >> 4, q = linear & 15;
            const float4 v = *(const float4*)(x + (size_t)(row0+row)*C_DIM + kbase + 4*q);
            uint32_t h01,h23,l01,l23;
            split2(v.x, v.y, h01, l01);
            split2(v.z, v.w, h23, l23);
            const int w = row*36 + 2*q;
            *(uint2*)&sXh[w] = make_uint2(h01, h23);
            *(uint2*)&sXl[w] = make_uint2(l01, l23);
        }
        // ---- load W tile: rows 0-127 = Uw, 128-255 = Bw; 64 k (4096 f4, 16/thread) ----
        #pragma unroll
        for(int it=0;it<16;it++){
            const int linear = tid + 256*it;
            const int row = linear >> 4, q = linear & 15;
            const float* src = (row < 128) ? (Uw + (size_t)row*C_DIM)
                                           : (Bw + (size_t)(row-128)*C_DIM);
            const float4 v = *(const float4*)(src + kbase + 4*q);
            uint32_t h01,h23,l01,l23;
            split2(v.x, v.y, h01, l01);
            split2(v.z, v.w, h23, l23);
            const int w = row*36 + 2*q;
            *(uint2*)&sWh[w] = make_uint2(h01, h23);
            *(uint2*)&sWl[w] = make_uint2(l01, l23);
        }
        __syncthreads();

        // ---- compute: 4 k16-steps ----
        #pragma unroll
        for(int ks=0;ks<4;ks++){
            const int kw = ks*8 + lc;          // k word offset (kk0/2 + lc)
            // A fragments for this warp's 4 m16 blocks (hi and lo)
            uint32_t Ah[4][4], Al[4][4];
            #pragma unroll
            for(int mi=0;mi<4;mi++){
                const int base = (mbase + mi*16 + lr)*36 + kw;
                Ah[mi][0]=sXh[base];     Ah[mi][2]=sXh[base+4];
                Ah[mi][1]=sXh[base+288]; Ah[mi][3]=sXh[base+292];
                Al[mi][0]=sXl[base];     Al[mi][2]=sXl[base+4];
                Al[mi][1]=sXl[base+288]; Al[mi][3]=sXl[base+292];
            }
            #pragma unroll
            for(int ni=0;ni<4;ni++){
                const int bu = (hbase + ni*8 + lr)*36 + kw;        // Uw rows
                const int bg = bu + 128*36;                        // Bw rows
                uint32_t Bhu[2], Blu[2], Bhg[2], Blg[2];
                Bhu[0]=sWh[bu]; Bhu[1]=sWh[bu+4];
                Blu[0]=sWl[bu]; Blu[1]=sWl[bu+4];
                Bhg[0]=sWh[bg]; Bhg[1]=sWh[bg+4];
                Blg[0]=sWl[bg]; Blg[1]=sWl[bg+4];
                #pragma unroll
                for(int mi=0;mi<4;mi++){
                    mma_bf16(cu[mi][ni], Ah[mi], Bhu);
                    mma_bf16(cu[mi][ni], Ah[mi], Blu);
                    mma_bf16(cu[mi][ni], Al[mi], Bhu);
                    mma_bf16(cg[mi][ni], Ah[mi], Bhg);
                    mma_bf16(cg[mi][ni], Ah[mi], Blg);
                    mma_bf16(cg[mi][ni], Al[mi], Bhg);
                }
            }
        }
    }

    // ---- epilogue: bias + sigmoid gate, write v ----
    #pragma unroll
    for(int ni=0;ni<4;ni++){
        const int h = hbase + ni*8 + 2*lc;
        const float ub0 = __ldg(Ub + h), ub1 = __ldg(Ub + h + 1);
        const float bb0 = __ldg(Bb + h), bb1 = __ldg(Bb + h + 1);
        #pragma unroll
        for(int mi=0;mi<4;mi++){
            const int tok = row0 + mbase + mi*16 + lr;
            {
                const float u0 = cu[mi][ni][0] + ub0, u1 = cu[mi][ni][1] + ub1;
                const float q0 = cg[mi][ni][0] + bb0, q1 = cg[mi][ni][1] + bb1;
                const float s0 = 1.f/(1.f+__expf(-q0));
                const float s1 = 1.f/(1.f+__expf(-q1));
                *(float2*)(g_v + (size_t)tok*H_DIM + h) = make_float2(s0*u0, s1*u1);
            }
            {
                const float u0 = cu[mi][ni][2] + ub0, u1 = cu[mi][ni][3] + ub1;
                const float q0 = cg[mi][ni][2] + bb0, q1 = cg[mi][ni][3] + bb1;
                const float s0 = 1.f/(1.f+__expf(-q0));
                const float s1 = 1.f/(1.f+__expf(-q1));
                *(float2*)(g_v + (size_t)(tok+8)*H_DIM + h) = make_float2(s0*u0, s1*u1);
            }
        }
    }
}

// ---------------- Kernel 2: 128x128 matrix square (for A^L) ----------------
__global__ __launch_bounds__(128) void ssm_matsq_kernel(const float* __restrict__ S,
                                                        float* __restrict__ D)
{
    __shared__ float row[H_DIM];
    const int i = blockIdx.x, j = threadIdx.x;
    row[j] = S[i*H_DIM + j];
    __syncthreads();
    float a0=0.f,a1=0.f,a2=0.f,a3=0.f;
    #pragma unroll 8
    for(int k=0;k<H_DIM;k+=4){
        a0 += row[k]   * S[(k  )*H_DIM + j];
        a1 += row[k+1] * S[(k+1)*H_DIM + j];
        a2 += row[k+2] * S[(k+2)*H_DIM + j];
        a3 += row[k+3] * S[(k+3)*H_DIM + j];
    }
    D[i*H_DIM + j] = (a0+a1)+(a2+a3);
}

// ---------------- Kernel 3: pass1 — local chunk scans (f32x2) ----------------
__global__ __launch_bounds__(128) void ssm_pass1_kernel(const float* __restrict__ Aw,
                                                        float* __restrict__ out)
{
    extern __shared__ float sm[];
    float* sA    = sm;                       // 128 x SA_PITCH
    float* hbuf0 = sm + H_DIM*SA_PITCH;      // 16 x 128
    float* hbuf1 = hbuf0 + B_DIM*H_DIM;
    const int i = threadIdx.x;
    const int c = blockIdx.x;

    #pragma unroll
    for(int j4=0;j4<32;j4++)
        *(float4*)&sA[i*SA_PITCH + 4*j4] = *(const float4*)(Aw + i*H_DIM + 4*j4);
    #pragma unroll
    for(int b=0;b<B_DIM;b++) hbuf0[b*H_DIM + i] = 0.f;
    __syncthreads();

    float* hc = hbuf0;
    float* hn = hbuf1;
    for(int k=0;k<L_CHUNK;k++){
        const int t = c*L_CHUNK + k;
        const float* vt = g_v + (size_t)t*(B_DIM*H_DIM);
        float vv[B_DIM];
        #pragma unroll
        for(int b=0;b<B_DIM;b++) vv[b] = vt[b*H_DIM + i];
        unsigned long long acc[B_DIM];
        #pragma unroll
        for(int b=0;b<B_DIM;b++) acc[b] = 0ull;
        #pragma unroll 4
        for(int j4=0;j4<32;j4++){
            const ulonglong2 a2 = *(const ulonglong2*)&sA[i*SA_PITCH + 4*j4];
            #pragma unroll
            for(int b=0;b<B_DIM;b++){
                const ulonglong2 h2 = *(const ulonglong2*)&hc[b*H_DIM + 4*j4];
                fma2(acc[b], a2.x, h2.x);
                fma2(acc[b], a2.y, h2.y);
            }
        }
        float* ot = out + (size_t)t*(B_DIM*H_DIM);
        #pragma unroll
        for(int b=0;b<B_DIM;b++){
            float lo, hi;
            upk2(acc[b], lo, hi);
            const float r = (lo + hi) + vv[b];
            hn[b*H_DIM + i] = r;
            ot[b*H_DIM + i] = r;
        }
        __syncthreads();
        float* tmp = hc; hc = hn; hn = tmp;
    }
    #pragma unroll
    for(int b=0;b<B_DIM;b++)
        g_ends[(c*B_DIM+b)*H_DIM + i] = hc[b*H_DIM + i];
}

// ---------------- Kernel 4: pass2 — carry chain, fully smem-resident ----------------
__global__ __launch_bounds__(128) void ssm_pass2_kernel()
{
    extern __shared__ float sm[];
    float* sAL = sm;                          // A^L, 128 x SA_PITCH
    float* sE  = sm + H_DIM*SA_PITCH;         // all chunk ends for this batch: 128 x 128
    __shared__ float sP[H_DIM];
    const int i = threadIdx.x;
    const int b = blockIdx.x;

    #pragma unroll
    for(int j4=0;j4<32;j4++)
        *(float4*)&sAL[i*SA_PITCH + 4*j4] = *(const float4*)(g_pw0 + i*H_DIM + 4*j4);
    #pragma unroll 8
    for(int c=0;c<NC;c++)
        sE[c*H_DIM + i] = g_ends[(c*B_DIM+b)*H_DIM + i];
    sP[i] = 0.f;
    float cur = 0.f;
    __syncthreads();

    for(int c=0;c<NC;c++){
        g_carry[(c*B_DIM+b)*H_DIM + i] = cur;          // incoming state for chunk c
        unsigned long long a0 = 0ull, a1 = 0ull;
        #pragma unroll 8
        for(int j4=0;j4<32;j4++){
            const ulonglong2 a2 = *(const ulonglong2*)&sAL[i*SA_PITCH + 4*j4];
            const ulonglong2 p2 = *(const ulonglong2*)&sP[4*j4];
            fma2(a0, a2.x, p2.x);
            fma2(a1, a2.y, p2.y);
        }
        float l0,h0,l1,h1;
        upk2(a0,l0,h0); upk2(a1,l1,h1);
        cur = sE[c*H_DIM + i] + ((l0+h0)+(l1+h1));
        __syncthreads();
        sP[i] = cur;
        __syncthreads();
    }
}

// ---------------- Kernel 5: pass3 — fixup h_t += A^{k+1} * carry (f32x2) ----------------
__global__ __launch_bounds__(128) void ssm_pass3_kernel(const float* __restrict__ Aw,
                                                        float* __restrict__ out)
{
    extern __shared__ float sm[];
    float* sA = sm;
    float* g0 = sm + H_DIM*SA_PITCH;
    float* g1 = g0 + B_DIM*H_DIM;
    const int i = threadIdx.x;
    const int c = blockIdx.x + 1;             // chunk 0 has zero carry

    #pragma unroll
    for(int j4=0;j4<32;j4++)
        *(float4*)&sA[i*SA_PITCH + 4*j4] = *(const float4*)(Aw + i*H_DIM + 4*j4);
    #pragma unroll
    for(int b=0;b<B_DIM;b++) g0[b*H_DIM + i] = g_carry[(c*B_DIM+b)*H_DIM + i];
    __syncthreads();

    float* gc = g0;
    float* gn = g1;
    for(int k=0;k<L_CHUNK;k++){
        const int t = c*L_CHUNK + k;
        float* ot = out + (size_t)t*(B_DIM*H_DIM);
        float ov[B_DIM];
        #pragma unroll
        for(int b=0;b<B_DIM;b++) ov[b] = ot[b*H_DIM + i];
        unsigned long long acc[B_DIM];
        #pragma unroll
        for(int b=0;b<B_DIM;b++) acc[b] = 0ull;
        #pragma unroll 4
        for(int j4=0;j4<32;j4++){
            const ulonglong2 a2 = *(const ulonglong2*)&sA[i*SA_PITCH + 4*j4];
            #pragma unroll
            for(int b=0;b<B_DIM;b++){
                const ulonglong2 h2 = *(const ulonglong2*)&gc[b*H_DIM + 4*j4];
                fma2(acc[b], a2.x, h2.x);
                fma2(acc[b], a2.y, h2.y);
            }
        }
        #pragma unroll
        for(int b=0;b<B_DIM;b++){
            float lo, hi;
            upk2(acc[b], lo, hi);
            const float r = lo + hi;
            gn[b*H_DIM + i] = r;
            ot[b*H_DIM + i] = ov[b] + r;
        }
        __syncthreads();
        float* tmp = gc; gc = gn; gn = tmp;
    }
}

// ---------------- launch ----------------
extern "C" void kernel_launch(void* const* d_in, const int* in_sizes, int n_in,
                              void* d_out, int out_size)
{
    const float* x  = (const float*)d_in[0];
    const float* Uw = (const float*)d_in[1];
    const float* Ub = (const float*)d_in[2];
    const float* Bw = (const float*)d_in[3];
    const float* Bb = (const float*)d_in[4];
    const float* Aw = (const float*)d_in[5];
    float* out = (float*)d_out;

    const int smem_pass = (H_DIM*SA_PITCH + 2*B_DIM*H_DIM) * 4;   // 83968 B
    const int smem_p2   = (H_DIM*SA_PITCH + NC*H_DIM) * 4;        // 133120 B
    cudaFuncSetAttribute(ssm_proj_mma,     cudaFuncAttributeMaxDynamicSharedMemorySize, PROJ_SMEM_BYTES);
    cudaFuncSetAttribute(ssm_pass1_kernel, cudaFuncAttributeMaxDynamicSharedMemorySize, smem_pass);
    cudaFuncSetAttribute(ssm_pass3_kernel, cudaFuncAttributeMaxDynamicSharedMemorySize, smem_pass);
    cudaFuncSetAttribute(ssm_pass2_kernel, cudaFuncAttributeMaxDynamicSharedMemorySize, smem_p2);

    // A^32 first (independent of proj) so the ncu capture (-s 5 -c 1, launch
    // index 5) lands on the projection kernel.
    void *pw0_v, *pw1_v;
    cudaGetSymbolAddress(&pw0_v, g_pw0);
    cudaGetSymbolAddress(&pw1_v, g_pw1);
    float* pw0 = (float*)pw0_v;
    float* pw1 = (float*)pw1_v;
    ssm_matsq_kernel<<<H_DIM,H_DIM>>>(Aw,  pw0);   // idx 0: A^2
    ssm_matsq_kernel<<<H_DIM,H_DIM>>>(pw0, pw1);   // idx 1: A^4
    ssm_matsq_kernel<<<H_DIM,H_DIM>>>(pw1, pw0);   // idx 2: A^8
    ssm_matsq_kernel<<<H_DIM,H_DIM>>>(pw0, pw1);   // idx 3: A^16
    ssm_matsq_kernel<<<H_DIM,H_DIM>>>(pw1, pw0);   // idx 4: A^32

    // idx 5: projection -> v (tensor-core bf16 split)  <-- ncu capture slot
    ssm_proj_mma<<<M_DIM/128, 256, PROJ_SMEM_BYTES>>>(x, Uw, Ub, Bw, Bb);

    // scans
    ssm_pass1_kernel<<<NC, 128, smem_pass>>>(Aw, out);
    ssm_pass2_kernel<<<B_DIM, 128, smem_p2>>>();
    ssm_pass3_kernel<<<NC-1, 128, smem_pass>>>(Aw, out);
}